// round 6
// baseline (speedup 1.0000x reference)
#include <cuda_runtime.h>
#include <cuda_fp16.h>
#include <cstdint>

// Problem dims (fixed by the dataset)
#define BATCH   8
#define MDIM    2048
#define KDIM    4096
#define NDIM    4096
#define MT      (BATCH * MDIM)          // 16384 rows total

// GEMM tiling (legacy mma.sync path — base sm_100, no tcgen05 available)
#define BM      256
#define BN      128
#define BK      64
#define KTILES  (KDIM / BK)             // 64
#define STAGES  4
#define PADK    80                      // smem row stride bytes (16B-aligned, conflict-free)
#define A_STAGE (BM * PADK)             // 20480
#define B_STAGE (BN * PADK)             // 10240
#define STAGE_BYTES (A_STAGE + B_STAGE) // 30720
#define SMEM_TOTAL  (STAGES * STAGE_BYTES)   // 122880
#define GEMM_THREADS 512                // 16 warps, 4x4 warp grid, warp tile 64x32

// int8 scratch (device globals: allocation-free rule)
__device__ __align__(1024) int8_t g_x8[(size_t)MT * KDIM];     // 64 MB, [MT, K] K-major
__device__ __align__(1024) int8_t g_y8t[(size_t)NDIM * KDIM];  // 16 MB, [N, K] K-major

// ---------------------------------------------------------------------------
// helpers
// ---------------------------------------------------------------------------
__device__ __forceinline__ void cp_async16(void* sptr, const void* gptr) {
    uint32_t saddr = (uint32_t)__cvta_generic_to_shared(sptr);
    asm volatile("cp.async.cg.shared.global [%0], [%1], 16;\n"
                 :: "r"(saddr), "l"(gptr) : "memory");
}
__device__ __forceinline__ void cp_commit() {
    asm volatile("cp.async.commit_group;\n" ::: "memory");
}
template <int N>
__device__ __forceinline__ void cp_wait() {
    asm volatile("cp.async.wait_group %0;\n" :: "n"(N) : "memory");
}

__device__ __forceinline__ void mma_s8(int* c, const uint32_t* a, const uint32_t* b) {
    asm volatile(
        "mma.sync.aligned.m16n8k32.row.col.s32.s8.s8.s32 "
        "{%0,%1,%2,%3}, {%4,%5,%6,%7}, {%8,%9}, {%0,%1,%2,%3};\n"
        : "+r"(c[0]), "+r"(c[1]), "+r"(c[2]), "+r"(c[3])
        : "r"(a[0]), "r"(a[1]), "r"(a[2]), "r"(a[3]), "r"(b[0]), "r"(b[1]));
}

// Round through fp16 (reference's final astype(float16)), emit as float32.
__device__ __forceinline__ float h16(float v) {
    return __half2float(__float2half_rn(v));
}

// ---------------------------------------------------------------------------
// Pack kernels
// ---------------------------------------------------------------------------
__device__ __forceinline__ uint32_t pack4(int4 a) {
    return (a.x & 0xff) | ((a.y & 0xff) << 8) | ((a.z & 0xff) << 16) | (a.w << 24);
}

// x int32 [MT, K] -> g_x8 int8 [MT, K], 16 elems/thread
__global__ void __launch_bounds__(256) pack_x_kernel(const int4* __restrict__ in) {
    size_t gid = (size_t)blockIdx.x * blockDim.x + threadIdx.x;
    const int4* p = in + gid * 4;
    int4 a = p[0], b = p[1], c = p[2], d = p[3];
    uint4 r;
    r.x = pack4(a); r.y = pack4(b); r.z = pack4(c); r.w = pack4(d);
    reinterpret_cast<uint4*>(g_x8)[gid] = r;
}

// y int32 [K, N] -> g_y8t int8 [N, K] (transpose) via 64x64 smem tiles
__global__ void __launch_bounds__(256) pack_yt_kernel(const int* __restrict__ y) {
    __shared__ __align__(16) int8_t tile[64 * 80];
    const int k0 = blockIdx.y * 64;
    const int n0 = blockIdx.x * 64;
    const int tid = threadIdx.x;
#pragma unroll
    for (int r = 0; r < 16; r++) {
        int e = r * 256 + tid;
        int k = e >> 6;
        int n = e & 63;
        tile[n * 80 + k] = (int8_t)y[(size_t)(k0 + k) * NDIM + n0 + n];
    }
    __syncthreads();
    int n = tid >> 2;
    int c = tid & 3;
    uint4 v = *reinterpret_cast<const uint4*>(&tile[n * 80 + c * 16]);
    *reinterpret_cast<uint4*>(&g_y8t[(size_t)(n0 + n) * KDIM + k0 + c * 16]) = v;
}

// ---------------------------------------------------------------------------
// GEMM: mma.sync int8, 256x128 block tile, 4-stage cp.async pipeline
// 16 warps in a 4(M)x4(N) grid; warp tile 64x32; mma atom m16n8k32.
// ---------------------------------------------------------------------------
__global__ void __launch_bounds__(GEMM_THREADS, 1)
gemm_i8_kernel(const float* __restrict__ scale_p, float* __restrict__ out) {
    extern __shared__ int8_t smem[];

    const int tid  = threadIdx.x;
    const int wid  = tid >> 5;
    const int lane = tid & 31;
    const int g    = lane >> 2;        // 0..7 row/col group
    const int t    = lane & 3;         // 0..3 k sub-chunk

    const int warp_m = (wid & 3) * 64;   // 4 warps over M
    const int warp_n = (wid >> 2) * 32;  // 4 warps over N

    const int m0 = blockIdx.y * BM;
    const int n0 = blockIdx.x * BN;

    // ---- producer addressing: 16B chunks ----
    const int ld_row = tid >> 2;         // 0..127
    const int ld_col = (tid & 3) * 16;   // 0,16,32,48
    const int8_t* gA0 = g_x8  + (size_t)(m0 + ld_row) * KDIM + ld_col;
    const int8_t* gA1 = gA0 + (size_t)128 * KDIM;
    const int8_t* gB  = g_y8t + (size_t)(n0 + ld_row) * KDIM + ld_col;

    int acc[4][4][4];                    // [im][in][reg]
#pragma unroll
    for (int i = 0; i < 4; i++)
#pragma unroll
        for (int j = 0; j < 4; j++)
#pragma unroll
            for (int r = 0; r < 4; r++) acc[i][j][r] = 0;

    auto load_stage = [&](int kt, int slot) {
        int8_t* sA = smem + slot * STAGE_BYTES;
        int8_t* sB = sA + A_STAGE;
        const size_t go = (size_t)kt * BK;
        cp_async16(sB + ld_row * PADK + ld_col,          gB  + go);   // B first: L2-resident operand
        cp_async16(sA + ld_row * PADK + ld_col,          gA0 + go);
        cp_async16(sA + (ld_row + 128) * PADK + ld_col,  gA1 + go);
        cp_commit();
    };

    // ---- prologue: fill STAGES-1 slots ----
#pragma unroll
    for (int s = 0; s < STAGES - 1; s++) load_stage(s, s);

    // ---- mainloop ----
    for (int kt = 0; kt < KTILES; kt++) {
        cp_wait<STAGES - 2>();
        __syncthreads();

        int nk = kt + STAGES - 1;
        if (nk < KTILES) load_stage(nk, nk % STAGES);

        const int slot = kt % STAGES;
        const int8_t* sA = smem + slot * STAGE_BYTES;
        const int8_t* sB = sA + A_STAGE;

#pragma unroll
        for (int ks = 0; ks < 2; ks++) {           // two K=32 steps per tile
            const int kb = ks * 32 + t * 4;
            uint32_t b[4][2];
#pragma unroll
            for (int in = 0; in < 4; in++) {
                const int8_t* p = sB + (warp_n + in * 8 + g) * PADK + kb;
                b[in][0] = *reinterpret_cast<const uint32_t*>(p);
                b[in][1] = *reinterpret_cast<const uint32_t*>(p + 16);
            }
#pragma unroll
            for (int im = 0; im < 4; im++) {
                uint32_t a[4];
                const int8_t* p = sA + (warp_m + im * 16 + g) * PADK + kb;
                a[0] = *reinterpret_cast<const uint32_t*>(p);
                a[1] = *reinterpret_cast<const uint32_t*>(p + 8 * PADK);
                a[2] = *reinterpret_cast<const uint32_t*>(p + 16);
                a[3] = *reinterpret_cast<const uint32_t*>(p + 8 * PADK + 16);
#pragma unroll
                for (int in = 0; in < 4; in++)
                    mma_s8(acc[im][in], a, b[in]);
            }
        }
    }

    // ---- epilogue: dequant, fp16-round, store as float32 ----
    const float sc = __ldg(scale_p);
#pragma unroll
    for (int im = 0; im < 4; im++) {
        const int mrow = m0 + warp_m + im * 16 + g;
        float* o0 = out + (size_t)mrow * NDIM + n0 + warp_n;
        float* o1 = o0 + (size_t)8 * NDIM;
#pragma unroll
        for (int in = 0; in < 4; in++) {
            const int col = in * 8 + 2 * t;
            float2 v0, v1;
            v0.x = h16((float)acc[im][in][0] * sc);
            v0.y = h16((float)acc[im][in][1] * sc);
            v1.x = h16((float)acc[im][in][2] * sc);
            v1.y = h16((float)acc[im][in][3] * sc);
            *reinterpret_cast<float2*>(o0 + col) = v0;
            *reinterpret_cast<float2*>(o1 + col) = v1;
        }
    }
}

// ---------------------------------------------------------------------------
// kernel_launch
// ---------------------------------------------------------------------------
extern "C" void kernel_launch(void* const* d_in, const int* in_sizes, int n_in,
                              void* d_out, int out_size) {
    const int*   x     = (const int*)d_in[0];
    const int*   y     = (const int*)d_in[1];
    const float* scale = (const float*)d_in[2];
    float*       out   = (float*)d_out;

    (void)in_sizes; (void)n_in; (void)out_size;

    // 1) pack x int32 -> int8 (64 MB scratch): 16 elems/thread
    pack_x_kernel<<<(int)((MT * (size_t)KDIM) / 16 / 256), 256>>>((const int4*)x);

    // 2) pack + transpose y [K,N] int32 -> [N,K] int8
    pack_yt_kernel<<<dim3(NDIM / 64, KDIM / 64), 256>>>(y);

    // 3) mma.sync int8 GEMM + fused dequant epilogue
    cudaFuncSetAttribute(gemm_i8_kernel, cudaFuncAttributeMaxDynamicSharedMemorySize, SMEM_TOTAL);
    gemm_i8_kernel<<<dim3(NDIM / BN, MT / BM), GEMM_THREADS, SMEM_TOTAL>>>(scale, out);
}

// round 8
// speedup vs baseline: 1.1228x; 1.1228x over previous
#include <cuda_runtime.h>
#include <cuda_fp16.h>
#include <cstdint>

// Problem dims (fixed by the dataset)
#define BATCH   8
#define MDIM    2048
#define KDIM    4096
#define NDIM    4096
#define MT      (BATCH * MDIM)          // 16384 rows total

// GEMM tiling (legacy mma.sync path — base sm_100, no tcgen05 available)
#define BM      256
#define BN      128
#define BK      64
#define KTILES  (KDIM / BK)             // 64
#define STAGES  4
#define PADK    80                      // smem row stride bytes (16B-aligned, conflict-free)
#define A_STAGE (BM * PADK)             // 20480
#define B_STAGE (BN * PADK)             // 10240
#define STAGE_BYTES (A_STAGE + B_STAGE) // 30720
#define SMEM_TOTAL  (STAGES * STAGE_BYTES)   // 122880
#define GEMM_THREADS 512                // 16 warps, 4x4 warp grid, warp tile 64x32

// int8 scratch (device globals: allocation-free rule)
__device__ __align__(1024) int8_t g_x8[(size_t)MT * KDIM];     // 64 MB, [MT, K] K-major
__device__ __align__(1024) int8_t g_y8t[(size_t)NDIM * KDIM];  // 16 MB, [N, K] K-major

// ---------------------------------------------------------------------------
// helpers
// ---------------------------------------------------------------------------
__device__ __forceinline__ void cp_async16(void* sptr, const void* gptr) {
    uint32_t saddr = (uint32_t)__cvta_generic_to_shared(sptr);
    asm volatile("cp.async.cg.shared.global [%0], [%1], 16;\n"
                 :: "r"(saddr), "l"(gptr) : "memory");
}
__device__ __forceinline__ void cp_commit() {
    asm volatile("cp.async.commit_group;\n" ::: "memory");
}
template <int N>
__device__ __forceinline__ void cp_wait() {
    asm volatile("cp.async.wait_group %0;\n" :: "n"(N) : "memory");
}

__device__ __forceinline__ void mma_s8(int* c, const uint32_t* a, uint32_t b0, uint32_t b1) {
    asm volatile(
        "mma.sync.aligned.m16n8k32.row.col.s32.s8.s8.s32 "
        "{%0,%1,%2,%3}, {%4,%5,%6,%7}, {%8,%9}, {%0,%1,%2,%3};\n"
        : "+r"(c[0]), "+r"(c[1]), "+r"(c[2]), "+r"(c[3])
        : "r"(a[0]), "r"(a[1]), "r"(a[2]), "r"(a[3]), "r"(b0), "r"(b1));
}

__device__ __forceinline__ void ldmatrix_x4(uint32_t* r, uint32_t saddr) {
    asm volatile("ldmatrix.sync.aligned.m8n8.x4.shared.b16 {%0,%1,%2,%3}, [%4];"
                 : "=r"(r[0]), "=r"(r[1]), "=r"(r[2]), "=r"(r[3]) : "r"(saddr));
}

// Round through fp16 (reference's final astype(float16)), emit as float32.
__device__ __forceinline__ float h16(float v) {
    return __half2float(__float2half_rn(v));
}

// ---------------------------------------------------------------------------
// Pack kernels
// ---------------------------------------------------------------------------
__device__ __forceinline__ uint32_t pack4(int4 a) {
    return (a.x & 0xff) | ((a.y & 0xff) << 8) | ((a.z & 0xff) << 16) | (a.w << 24);
}

// x int32 [MT, K] -> g_x8 int8 [MT, K], 16 elems/thread
__global__ void __launch_bounds__(256) pack_x_kernel(const int4* __restrict__ in) {
    size_t gid = (size_t)blockIdx.x * blockDim.x + threadIdx.x;
    const int4* p = in + gid * 4;
    int4 a = p[0], b = p[1], c = p[2], d = p[3];
    uint4 r;
    r.x = pack4(a); r.y = pack4(b); r.z = pack4(c); r.w = pack4(d);
    reinterpret_cast<uint4*>(g_x8)[gid] = r;
}

// y int32 [K, N] -> g_y8t int8 [N, K] (transpose) via 64x64 smem tiles
__global__ void __launch_bounds__(256) pack_yt_kernel(const int* __restrict__ y) {
    __shared__ __align__(16) int8_t tile[64 * 80];
    const int k0 = blockIdx.y * 64;
    const int n0 = blockIdx.x * 64;
    const int tid = threadIdx.x;
#pragma unroll
    for (int r = 0; r < 16; r++) {
        int e = r * 256 + tid;
        int k = e >> 6;
        int n = e & 63;
        tile[n * 80 + k] = (int8_t)y[(size_t)(k0 + k) * NDIM + n0 + n];
    }
    __syncthreads();
    int n = tid >> 2;
    int c = tid & 3;
    uint4 v = *reinterpret_cast<const uint4*>(&tile[n * 80 + c * 16]);
    *reinterpret_cast<uint4*>(&g_y8t[(size_t)(n0 + n) * KDIM + k0 + c * 16]) = v;
}

// dummy kernel: shifts launch-period so ncu's fixed skip may land on the GEMM
__global__ void probe_kernel() {}

// ---------------------------------------------------------------------------
// GEMM: mma.sync int8, 256x128 block tile, 4-stage cp.async pipeline
// 16 warps in a 4(M)x4(N) grid; warp tile 64x32; mma atom m16n8k32.
// Fragment loads via ldmatrix.x4 (12 LDSM/kt/warp vs 48 LDS.32).
// ---------------------------------------------------------------------------
__global__ void __launch_bounds__(GEMM_THREADS, 1)
gemm_i8_kernel(const float* __restrict__ scale_p, float* __restrict__ out) {
    extern __shared__ int8_t smem[];

    const int tid  = threadIdx.x;
    const int wid  = tid >> 5;
    const int lane = tid & 31;
    const int g    = lane >> 2;        // 0..7 row/col group
    const int t    = lane & 3;         // 0..3 k sub-chunk

    const int warp_m = (wid & 3) * 64;   // 4 warps over M
    const int warp_n = (wid >> 2) * 32;  // 4 warps over N

    const int m0 = blockIdx.y * BM;
    const int n0 = blockIdx.x * BN;

    const uint32_t smem_b = (uint32_t)__cvta_generic_to_shared(smem);

    // ldmatrix per-thread row offsets (within a stage)
    // A (x4, 16x32 s8 tile): mats = [rows0-7|rows8-15] x [bytes0-15|bytes16-31]
    uint32_t offA[4];
#pragma unroll
    for (int im = 0; im < 4; im++)
        offA[im] = (uint32_t)((warp_m + im * 16 + (lane & 15)) * PADK + (lane >> 4) * 16);
    // B (x4 covering two n-fragments): mats = in0[b0-15], in0[b16-31], in1[b0-15], in1[b16-31]
    uint32_t offB[2];
#pragma unroll
    for (int p = 0; p < 2; p++)
        offB[p] = (uint32_t)(A_STAGE +
                   (warp_n + p * 16 + ((lane >> 4) & 1) * 8 + (lane & 7)) * PADK +
                   ((lane >> 3) & 1) * 16);

    // ---- producer addressing: 16B chunks ----
    const int ld_row = tid >> 2;         // 0..127
    const int ld_col = (tid & 3) * 16;   // 0,16,32,48
    const int8_t* gA0 = g_x8  + (size_t)(m0 + ld_row) * KDIM + ld_col;
    const int8_t* gA1 = gA0 + (size_t)128 * KDIM;
    const int8_t* gB  = g_y8t + (size_t)(n0 + ld_row) * KDIM + ld_col;

    int acc[4][4][4];                    // [im][in][reg]
#pragma unroll
    for (int i = 0; i < 4; i++)
#pragma unroll
        for (int j = 0; j < 4; j++)
#pragma unroll
            for (int r = 0; r < 4; r++) acc[i][j][r] = 0;

    auto load_stage = [&](int kt, int slot) {
        int8_t* sA = smem + slot * STAGE_BYTES;
        int8_t* sB = sA + A_STAGE;
        const size_t go = (size_t)kt * BK;
        cp_async16(sB + ld_row * PADK + ld_col,          gB  + go);   // B first: L2-resident operand
        cp_async16(sA + ld_row * PADK + ld_col,          gA0 + go);
        cp_async16(sA + (ld_row + 128) * PADK + ld_col,  gA1 + go);
        cp_commit();
    };

    // ---- prologue: fill STAGES-1 slots ----
#pragma unroll
    for (int s = 0; s < STAGES - 1; s++) load_stage(s, s);

    // ---- mainloop ----
    for (int kt = 0; kt < KTILES; kt++) {
        cp_wait<STAGES - 2>();
        __syncthreads();

        int nk = kt + STAGES - 1;
        if (nk < KTILES) load_stage(nk, nk % STAGES);

        const uint32_t sbase = smem_b + (uint32_t)((kt % STAGES) * STAGE_BYTES);

#pragma unroll
        for (int ks = 0; ks < 2; ks++) {           // two K=32 steps per tile
            const uint32_t kb = (uint32_t)(ks * 32);
            uint32_t a[4][4], b[2][4];
#pragma unroll
            for (int im = 0; im < 4; im++) ldmatrix_x4(a[im], sbase + offA[im] + kb);
#pragma unroll
            for (int p = 0; p < 2; p++)    ldmatrix_x4(b[p],  sbase + offB[p]  + kb);
#pragma unroll
            for (int im = 0; im < 4; im++) {
                mma_s8(acc[im][0], a[im], b[0][0], b[0][1]);
                mma_s8(acc[im][1], a[im], b[0][2], b[0][3]);
                mma_s8(acc[im][2], a[im], b[1][0], b[1][1]);
                mma_s8(acc[im][3], a[im], b[1][2], b[1][3]);
            }
        }
    }

    // ---- epilogue: dequant, fp16-round, store as float32 ----
    const float sc = __ldg(scale_p);
#pragma unroll
    for (int im = 0; im < 4; im++) {
        const int mrow = m0 + warp_m + im * 16 + g;
        float* o0 = out + (size_t)mrow * NDIM + n0 + warp_n;
        float* o1 = o0 + (size_t)8 * NDIM;
#pragma unroll
        for (int in = 0; in < 4; in++) {
            const int col = in * 8 + 2 * t;
            float2 v0, v1;
            v0.x = h16((float)acc[im][in][0] * sc);
            v0.y = h16((float)acc[im][in][1] * sc);
            v1.x = h16((float)acc[im][in][2] * sc);
            v1.y = h16((float)acc[im][in][3] * sc);
            *reinterpret_cast<float2*>(o0 + col) = v0;
            *reinterpret_cast<float2*>(o1 + col) = v1;
        }
    }
}

// ---------------------------------------------------------------------------
// kernel_launch
// ---------------------------------------------------------------------------
extern "C" void kernel_launch(void* const* d_in, const int* in_sizes, int n_in,
                              void* d_out, int out_size) {
    const int*   x     = (const int*)d_in[0];
    const int*   y     = (const int*)d_in[1];
    const float* scale = (const float*)d_in[2];
    float*       out   = (float*)d_out;

    (void)in_sizes; (void)n_in; (void)out_size;

    // 1) pack x int32 -> int8 (64 MB scratch): 16 elems/thread
    pack_x_kernel<<<(int)((MT * (size_t)KDIM) / 16 / 256), 256>>>((const int4*)x);

    // 2) pack + transpose y [K,N] int32 -> [N,K] int8
    pack_yt_kernel<<<dim3(NDIM / 64, KDIM / 64), 256>>>(y);

    // 3) mma.sync int8 GEMM + fused dequant epilogue
    cudaFuncSetAttribute(gemm_i8_kernel, cudaFuncAttributeMaxDynamicSharedMemorySize, SMEM_TOTAL);
    gemm_i8_kernel<<<dim3(NDIM / BN, MT / BM), GEMM_THREADS, SMEM_TOTAL>>>(scale, out);

    // 4) no-op: shifts launch period so the profiler's fixed skip can hit the GEMM
    probe_kernel<<<1, 32>>>();
}

// round 9
// speedup vs baseline: 1.2077x; 1.0756x over previous
#include <cuda_runtime.h>
#include <cuda_fp16.h>
#include <cstdint>

// Problem dims (fixed by the dataset)
#define BATCH   8
#define MDIM    2048
#define KDIM    4096
#define NDIM    4096
#define MT      (BATCH * MDIM)          // 16384 rows total

// GEMM tiling (legacy mma.sync path — base sm_100, no tcgen05 available)
#define BM      128
#define BN      128
#define BK      64
#define KTILES  (KDIM / BK)             // 64
#define STAGES  4
#define PADK    80                      // smem row stride bytes (16B-aligned, conflict-free)
#define A_STAGE (BM * PADK)             // 10240
#define B_STAGE (BN * PADK)             // 10240
#define STAGE_BYTES (A_STAGE + B_STAGE) // 20480
#define SMEM_TOTAL  (STAGES * STAGE_BYTES)   // 81920 -> 2 CTAs/SM
#define GEMM_THREADS 256                // 8 warps, 2(M)x4(N) grid, warp tile 64x32

// int8 scratch (device globals: allocation-free rule)
__device__ __align__(1024) int8_t g_x8[(size_t)MT * KDIM];     // 64 MB, [MT, K] K-major
__device__ __align__(1024) int8_t g_y8t[(size_t)NDIM * KDIM];  // 16 MB, [N, K] K-major

// ---------------------------------------------------------------------------
// helpers
// ---------------------------------------------------------------------------
__device__ __forceinline__ void cp_async16(void* sptr, const void* gptr) {
    uint32_t saddr = (uint32_t)__cvta_generic_to_shared(sptr);
    asm volatile("cp.async.cg.shared.global [%0], [%1], 16;\n"
                 :: "r"(saddr), "l"(gptr) : "memory");
}
__device__ __forceinline__ void cp_commit() {
    asm volatile("cp.async.commit_group;\n" ::: "memory");
}
template <int N>
__device__ __forceinline__ void cp_wait() {
    asm volatile("cp.async.wait_group %0;\n" :: "n"(N) : "memory");
}

__device__ __forceinline__ void mma_s8(int* c, const uint32_t* a, uint32_t b0, uint32_t b1) {
    asm volatile(
        "mma.sync.aligned.m16n8k32.row.col.s32.s8.s8.s32 "
        "{%0,%1,%2,%3}, {%4,%5,%6,%7}, {%8,%9}, {%0,%1,%2,%3};\n"
        : "+r"(c[0]), "+r"(c[1]), "+r"(c[2]), "+r"(c[3])
        : "r"(a[0]), "r"(a[1]), "r"(a[2]), "r"(a[3]), "r"(b0), "r"(b1));
}

__device__ __forceinline__ void ldmatrix_x4(uint32_t* r, uint32_t saddr) {
    asm volatile("ldmatrix.sync.aligned.m8n8.x4.shared.b16 {%0,%1,%2,%3}, [%4];"
                 : "=r"(r[0]), "=r"(r[1]), "=r"(r[2]), "=r"(r[3]) : "r"(saddr));
}

// Round through fp16 (reference's final astype(float16)), emit as float32.
__device__ __forceinline__ float h16(float v) {
    return __half2float(__float2half_rn(v));
}

// ---------------------------------------------------------------------------
// Pack kernels
// ---------------------------------------------------------------------------
__device__ __forceinline__ uint32_t pack4(int4 a) {
    return (a.x & 0xff) | ((a.y & 0xff) << 8) | ((a.z & 0xff) << 16) | (a.w << 24);
}

// x int32 [MT, K] -> g_x8 int8 [MT, K], 16 elems/thread
__global__ void __launch_bounds__(256) pack_x_kernel(const int4* __restrict__ in) {
    size_t gid = (size_t)blockIdx.x * blockDim.x + threadIdx.x;
    const int4* p = in + gid * 4;
    int4 a = p[0], b = p[1], c = p[2], d = p[3];
    uint4 r;
    r.x = pack4(a); r.y = pack4(b); r.z = pack4(c); r.w = pack4(d);
    reinterpret_cast<uint4*>(g_x8)[gid] = r;
}

// y int32 [K, N] -> g_y8t int8 [N, K] (transpose) via 64x64 smem tiles
__global__ void __launch_bounds__(256) pack_yt_kernel(const int* __restrict__ y) {
    __shared__ __align__(16) int8_t tile[64 * 80];
    const int k0 = blockIdx.y * 64;
    const int n0 = blockIdx.x * 64;
    const int tid = threadIdx.x;
#pragma unroll
    for (int r = 0; r < 16; r++) {
        int e = r * 256 + tid;
        int k = e >> 6;
        int n = e & 63;
        tile[n * 80 + k] = (int8_t)y[(size_t)(k0 + k) * NDIM + n0 + n];
    }
    __syncthreads();
    int n = tid >> 2;
    int c = tid & 3;
    uint4 v = *reinterpret_cast<const uint4*>(&tile[n * 80 + c * 16]);
    *reinterpret_cast<uint4*>(&g_y8t[(size_t)(n0 + n) * KDIM + k0 + c * 16]) = v;
}

// dummy kernel: positions the GEMM at ncu's capture index (0-based launch 3)
__global__ void probe_kernel() {}

// ---------------------------------------------------------------------------
// GEMM: mma.sync int8, 128x128 block tile, 4-stage cp.async pipeline,
// 2 CTAs/SM. 8 warps in 2(M)x4(N) grid; warp tile 64x32; atom m16n8k32.
// Fragment loads via ldmatrix.x4.
// ---------------------------------------------------------------------------
__global__ void __launch_bounds__(GEMM_THREADS, 2)
gemm_i8_kernel(const float* __restrict__ scale_p, float* __restrict__ out) {
    extern __shared__ int8_t smem[];

    const int tid  = threadIdx.x;
    const int wid  = tid >> 5;
    const int lane = tid & 31;
    const int g    = lane >> 2;        // 0..7 row/col group
    const int t    = lane & 3;         // 0..3 k sub-chunk

    const int warp_m = (wid & 1) * 64;   // 2 warps over M
    const int warp_n = (wid >> 1) * 32;  // 4 warps over N

    const int m0 = blockIdx.y * BM;
    const int n0 = blockIdx.x * BN;

    const uint32_t smem_b = (uint32_t)__cvta_generic_to_shared(smem);

    // ldmatrix per-thread offsets (within a stage)
    uint32_t offA[4];
#pragma unroll
    for (int im = 0; im < 4; im++)
        offA[im] = (uint32_t)((warp_m + im * 16 + (lane & 15)) * PADK + (lane >> 4) * 16);
    uint32_t offB[2];
#pragma unroll
    for (int p = 0; p < 2; p++)
        offB[p] = (uint32_t)(A_STAGE +
                   (warp_n + p * 16 + ((lane >> 4) & 1) * 8 + (lane & 7)) * PADK +
                   ((lane >> 3) & 1) * 16);

    // ---- producer addressing: 16B chunks, 256 threads ----
    // A: 128 rows x 4 chunks = 512 xfers (2/thread); B same.
    const int ld_row = tid >> 2;         // 0..63
    const int ld_col = (tid & 3) * 16;   // 0,16,32,48
    const int8_t* gA0 = g_x8  + (size_t)(m0 + ld_row) * KDIM + ld_col;
    const int8_t* gA1 = gA0 + (size_t)64 * KDIM;
    const int8_t* gB0 = g_y8t + (size_t)(n0 + ld_row) * KDIM + ld_col;
    const int8_t* gB1 = gB0 + (size_t)64 * KDIM;

    int acc[4][4][4];                    // [im][in][reg]
#pragma unroll
    for (int i = 0; i < 4; i++)
#pragma unroll
        for (int j = 0; j < 4; j++)
#pragma unroll
            for (int r = 0; r < 4; r++) acc[i][j][r] = 0;

    auto load_stage = [&](int kt, int slot) {
        int8_t* sA = smem + slot * STAGE_BYTES;
        int8_t* sB = sA + A_STAGE;
        const size_t go = (size_t)kt * BK;
        cp_async16(sB + ld_row * PADK + ld_col,         gB0 + go);  // B first: L2-resident
        cp_async16(sB + (ld_row + 64) * PADK + ld_col,  gB1 + go);
        cp_async16(sA + ld_row * PADK + ld_col,         gA0 + go);
        cp_async16(sA + (ld_row + 64) * PADK + ld_col,  gA1 + go);
        cp_commit();
    };

    // ---- prologue: fill STAGES-1 slots ----
#pragma unroll
    for (int s = 0; s < STAGES - 1; s++) load_stage(s, s);

    // ---- mainloop ----
    for (int kt = 0; kt < KTILES; kt++) {
        cp_wait<STAGES - 2>();
        __syncthreads();

        int nk = kt + STAGES - 1;
        if (nk < KTILES) load_stage(nk, nk % STAGES);

        const uint32_t sbase = smem_b + (uint32_t)((kt % STAGES) * STAGE_BYTES);

#pragma unroll
        for (int ks = 0; ks < 2; ks++) {           // two K=32 steps per tile
            const uint32_t kb = (uint32_t)(ks * 32);
            uint32_t a[4][4], b[2][4];
#pragma unroll
            for (int im = 0; im < 4; im++) ldmatrix_x4(a[im], sbase + offA[im] + kb);
#pragma unroll
            for (int p = 0; p < 2; p++)    ldmatrix_x4(b[p],  sbase + offB[p]  + kb);
#pragma unroll
            for (int im = 0; im < 4; im++) {
                mma_s8(acc[im][0], a[im], b[0][0], b[0][1]);
                mma_s8(acc[im][1], a[im], b[0][2], b[0][3]);
                mma_s8(acc[im][2], a[im], b[1][0], b[1][1]);
                mma_s8(acc[im][3], a[im], b[1][2], b[1][3]);
            }
        }
    }

    // ---- epilogue: dequant, fp16-round, store as float32 ----
    const float sc = __ldg(scale_p);
#pragma unroll
    for (int im = 0; im < 4; im++) {
        const int mrow = m0 + warp_m + im * 16 + g;
        float* o0 = out + (size_t)mrow * NDIM + n0 + warp_n;
        float* o1 = o0 + (size_t)8 * NDIM;
#pragma unroll
        for (int in = 0; in < 4; in++) {
            const int col = in * 8 + 2 * t;
            float2 v0, v1;
            v0.x = h16((float)acc[im][in][0] * sc);
            v0.y = h16((float)acc[im][in][1] * sc);
            v1.x = h16((float)acc[im][in][2] * sc);
            v1.y = h16((float)acc[im][in][3] * sc);
            *reinterpret_cast<float2*>(o0 + col) = v0;
            *reinterpret_cast<float2*>(o1 + col) = v1;
        }
    }
}

// ---------------------------------------------------------------------------
// kernel_launch
// ---------------------------------------------------------------------------
extern "C" void kernel_launch(void* const* d_in, const int* in_sizes, int n_in,
                              void* d_out, int out_size) {
    const int*   x     = (const int*)d_in[0];
    const int*   y     = (const int*)d_in[1];
    const float* scale = (const float*)d_in[2];
    float*       out   = (float*)d_out;

    (void)in_sizes; (void)n_in; (void)out_size;

    // 1) pack x int32 -> int8 (64 MB scratch)
    pack_x_kernel<<<(int)((MT * (size_t)KDIM) / 16 / 256), 256>>>((const int4*)x);

    // 2) pack + transpose y [K,N] int32 -> [N,K] int8
    pack_yt_kernel<<<dim3(NDIM / 64, KDIM / 64), 256>>>(y);

    // 3) probe: places the GEMM at ncu's captured launch index (3)
    probe_kernel<<<1, 32>>>();

    // 4) mma.sync int8 GEMM + fused dequant epilogue
    cudaFuncSetAttribute(gemm_i8_kernel, cudaFuncAttributeMaxDynamicSharedMemorySize, SMEM_TOTAL);
    gemm_i8_kernel<<<dim3(NDIM / BN, MT / BM), GEMM_THREADS, SMEM_TOTAL>>>(scale, out);
}